// round 11
// baseline (speedup 1.0000x reference)
#include <cuda_runtime.h>

#define BB 128
#define TT 256
#define DD 256
#define UU 256
#define ZZ 1024   // 4*U
#define NCTA 256

// ---------------- scratch (device globals; no allocation allowed) ----------------
__device__ float g_xz[2][TT * BB * ZZ];       // [dir][t][b][u*4+g]
__device__ float g_h0[2][TT * BB * UU];       // layer-0 outputs [dir][t][b][u]
__device__ float g_h1[2][TT * BB * UU];       // layer-1 raw lstm outputs
__device__ float g_hT[2][2][UU * BB];         // [buf][dir][u][b] double-buffered h^T
__device__ float g_Wp[2][2][DD * ZZ];         // [layer][dir][k][u*4+g]
__device__ float g_Rp[2][2][UU * ZZ];         // [layer][dir][k][u*4+g]
__device__ float g_bp[2][2][ZZ];
__device__ int g_count[8];                    // per-group barrier (dir x batch-quarter)
__device__ int g_gen[8];

// ---------------- packed f32x2 (FFMA2) helpers ------------------------------------
__device__ __forceinline__ void fma2(unsigned long long& d, unsigned long long a,
                                     unsigned long long b) {
    asm("fma.rn.f32x2 %0, %1, %2, %0;" : "+l"(d) : "l"(a), "l"(b));
}
__device__ __forceinline__ void add2(unsigned long long& d, unsigned long long a) {
    asm("add.rn.f32x2 %0, %0, %1;" : "+l"(d) : "l"(a));
}
__device__ __forceinline__ unsigned long long pack2(float x) {
    unsigned long long d; unsigned int u = __float_as_uint(x);
    asm("mov.b64 %0, {%1, %1};" : "=l"(d) : "r"(u));
    return d;
}
__device__ __forceinline__ void unpack2(unsigned long long v, float& lo, float& hi) {
    unsigned int a, b;
    asm("mov.b64 {%0, %1}, %2;" : "=r"(a), "=r"(b) : "l"(v));
    lo = __uint_as_float(a); hi = __uint_as_float(b);
}

// ---------------- acquire/release barrier primitives -------------------------------
__device__ __forceinline__ int atom_add_acqrel(int* p) {
    int old;
    asm volatile("atom.acq_rel.gpu.global.add.s32 %0, [%1], 1;"
                 : "=r"(old) : "l"(p) : "memory");
    return old;
}
__device__ __forceinline__ void st_release(int* p, int v) {
    asm volatile("st.release.gpu.global.s32 [%0], %1;" :: "l"(p), "r"(v) : "memory");
}
__device__ __forceinline__ int ld_acquire(int* p) {
    int v;
    asm volatile("ld.acquire.gpu.global.s32 %0, [%1];" : "=r"(v) : "l"(p) : "memory");
    return v;
}

// ---------------- cp.async helpers -------------------------------------------------
__device__ __forceinline__ void cpa16(void* smem, const void* g) {
    unsigned s = (unsigned)__cvta_generic_to_shared(smem);
    asm volatile("cp.async.cg.shared.global [%0], [%1], 16;" :: "r"(s), "l"(g));
}
__device__ __forceinline__ void cpa_commit() { asm volatile("cp.async.commit_group;"); }
__device__ __forceinline__ void cpa_wait0()  { asm volatile("cp.async.wait_group 0;"); }

// ---------------- MUFU-free fast math ---------------------------------------------
__device__ __forceinline__ float fast_exp(float x) {
    x = fminf(fmaxf(x, -80.0f), 80.0f);
    float y = x * 1.442695041f;
    float t = y + 12582912.0f;
    float n = t - 12582912.0f;
    float f = y - n;
    int   ni = __float_as_int(t) - 0x4B400000;
    float p = 1.54035304e-4f;
    p = fmaf(p, f, 1.33335581e-3f);
    p = fmaf(p, f, 9.61812910e-3f);
    p = fmaf(p, f, 5.55041087e-2f);
    p = fmaf(p, f, 2.40226507e-1f);
    p = fmaf(p, f, 6.93147182e-1f);
    p = fmaf(p, f, 1.0f);
    return p * __int_as_float((ni + 127) << 23);
}
__device__ __forceinline__ float fast_rcp(float a) {
    float r = __int_as_float(0x7EF311C3 - __float_as_int(a));
    r = r * fmaf(-a, r, 2.0f);
    r = r * fmaf(-a, r, 2.0f);
    r = r * fmaf(-a, r, 2.0f);
    return r;
}
__device__ __forceinline__ float sigm_(float x) { return fast_rcp(1.0f + fast_exp(-x)); }
__device__ __forceinline__ float tanh_(float x) { return fmaf(-2.0f, fast_rcp(1.0f + fast_exp(2.0f * x)), 1.0f); }

// ---------------- weight permutation: col (g*256+u) -> (u*4+g) --------------------
__global__ void prep_kernel(const float* __restrict__ kfw, const float* __restrict__ rfw,
                            const float* __restrict__ bfw, const float* __restrict__ kbw,
                            const float* __restrict__ rbw, const float* __restrict__ bbw) {
    int idx = blockIdx.x * blockDim.x + threadIdx.x;
    if (idx >= 2 * 2 * DD * ZZ) return;
    int e  = idx & (DD * ZZ - 1);
    int ld = idx >> 18;
    int l = ld >> 1, d = ld & 1;
    int k  = e >> 10;
    int uu = e & 1023;
    int u = uu >> 2, g = uu & 3;
    int src_col = g * UU + u;
    const float* Ksrc = d ? kbw : kfw;
    const float* Rsrc = d ? rbw : rfw;
    g_Wp[l][d][e] = Ksrc[l * DD * ZZ + k * ZZ + src_col];
    g_Rp[l][d][e] = Rsrc[l * UU * ZZ + k * ZZ + src_col];
    if (k == 0) {
        const float* bsrc = d ? bbw : bfw;
        g_bp[l][d][uu] = bsrc[l * ZZ + src_col];
    }
}

__global__ void zero_bar_kernel() {
    if (threadIdx.x < 8) { g_count[threadIdx.x] = 0; g_gen[threadIdx.x] = 0; }
}

// ---------------- input projection (FFMA2, cp.async double buffer, KTILE=16) -------
__global__ __launch_bounds__(256, 2) void proj_kernel(const float* __restrict__ x, int layer) {
    int dir = blockIdx.z;
    const float* A  = (layer == 0) ? x : g_h0[dir];
    const float* Wp = g_Wp[layer][dir];
    const float* bp = g_bp[layer][dir];
    float* C = g_xz[dir];
    const int m0 = blockIdx.y * 128;
    const int n0 = blockIdx.x * 128;
    __shared__ float As[2][16][128];
    __shared__ float Bs[2][16][128];
    int tid = threadIdx.x;
    int tm = (tid >> 4) << 3;
    int tn = (tid & 15) << 3;
    unsigned long long acc2[8][4];
#pragma unroll
    for (int i = 0; i < 8; i++)
#pragma unroll
        for (int j = 0; j < 4; j++) acc2[i][j] = 0ULL;

    int arow = tid >> 1, akq = (tid & 1) << 3;
    int brow = tid >> 4, bc = (tid & 15) << 3;
    const float* Ap = A + (size_t)(m0 + arow) * DD + akq;
    const float* Bp = Wp + (size_t)brow * ZZ + n0 + bc;

    {
        float4 a0 = *(const float4*)Ap;
        float4 a1 = *(const float4*)(Ap + 4);
        As[0][akq + 0][arow] = a0.x; As[0][akq + 1][arow] = a0.y;
        As[0][akq + 2][arow] = a0.z; As[0][akq + 3][arow] = a0.w;
        As[0][akq + 4][arow] = a1.x; As[0][akq + 5][arow] = a1.y;
        As[0][akq + 6][arow] = a1.z; As[0][akq + 7][arow] = a1.w;
    }
    cpa16(&Bs[0][brow][bc], Bp);
    cpa16(&Bs[0][brow][bc + 4], Bp + 4);
    cpa_commit();
    float4 av0 = *(const float4*)(Ap + 16);
    float4 av1 = *(const float4*)(Ap + 20);

    for (int it = 0; it < 16; it++) {
        int cur = it & 1, nxt = cur ^ 1;
        cpa_wait0();
        __syncthreads();
        if (it < 15) {
            As[nxt][akq + 0][arow] = av0.x; As[nxt][akq + 1][arow] = av0.y;
            As[nxt][akq + 2][arow] = av0.z; As[nxt][akq + 3][arow] = av0.w;
            As[nxt][akq + 4][arow] = av1.x; As[nxt][akq + 5][arow] = av1.y;
            As[nxt][akq + 6][arow] = av1.z; As[nxt][akq + 7][arow] = av1.w;
            cpa16(&Bs[nxt][brow][bc], Bp + (size_t)(it + 1) * 16 * ZZ);
            cpa16(&Bs[nxt][brow][bc + 4], Bp + (size_t)(it + 1) * 16 * ZZ + 4);
            cpa_commit();
            if (it < 14) {
                av0 = *(const float4*)(Ap + (it + 2) * 16);
                av1 = *(const float4*)(Ap + (it + 2) * 16 + 4);
            }
        }
#pragma unroll
        for (int kk = 0; kk < 16; kk++) {
            float a[8];
            *(float4*)&a[0] = *(float4*)&As[cur][kk][tm];
            *(float4*)&a[4] = *(float4*)&As[cur][kk][tm + 4];
            ulonglong2 b01 = *(const ulonglong2*)&Bs[cur][kk][tn];
            ulonglong2 b23 = *(const ulonglong2*)&Bs[cur][kk][tn + 4];
#pragma unroll
            for (int i = 0; i < 8; i++) {
                unsigned long long ai = pack2(a[i]);
                fma2(acc2[i][0], ai, b01.x);
                fma2(acc2[i][1], ai, b01.y);
                fma2(acc2[i][2], ai, b23.x);
                fma2(acc2[i][3], ai, b23.y);
            }
        }
    }
    float bv[8];
#pragma unroll
    for (int j = 0; j < 8; j++) bv[j] = bp[n0 + tn + j];
#pragma unroll
    for (int i = 0; i < 8; i++) {
        int m = m0 + tm + i;
        int crow = (layer == 0) ? ((m & 255) * BB + (m >> 8)) : m;
        float* cp = C + (size_t)crow * ZZ + n0 + tn;
        float c0, c1, c2, c3, c4, c5, c6, c7;
        unpack2(acc2[i][0], c0, c1);
        unpack2(acc2[i][1], c2, c3);
        unpack2(acc2[i][2], c4, c5);
        unpack2(acc2[i][3], c6, c7);
        float4 v0, v1;
        v0.x = c0 + bv[0]; v0.y = c1 + bv[1]; v0.z = c2 + bv[2]; v0.w = c3 + bv[3];
        v1.x = c4 + bv[4]; v1.y = c5 + bv[5]; v1.z = c6 + bv[6]; v1.w = c7 + bv[7];
        *(float4*)cp = v0;
        *(float4*)(cp + 4) = v1;
    }
}

// ---------------- persistent recurrence scan (one launch per layer) ----------------
// grid 256 CTAs x 256 threads, 2 CTAs/SM. CTA = (dir, batch-quarter 32b, z-slice
// 32zc = 8 units). Barrier groups of 32 CTAs sharing (dir,bq). R (natural gate
// pairs) + h (duplicated) in smem -> inner loop is 2 LDS.128 + 4 FFMA2 per k,
// no pack MOVs. Co-resident CTA pairs hide each other's fill/barrier latency.
__global__ __launch_bounds__(256, 2) void scan_kernel(int layer) {
    extern __shared__ float sm[];
    float* Rs = sm;                                   // [256 k][32 zc] = 32 KB
    float* hs = sm + 256 * 32;                        // [256 k][64] dup = 64 KB
    unsigned long long* red = (unsigned long long*)(hs + 256 * 64);  // 256*4 = 8 KB
    float* stage = (float*)(red + 256 * 4);           // [8][33]+pad ~ 1.1 KB

    int bid = blockIdx.x;
    int dir = bid >> 7;
    int bq  = (bid >> 5) & 3;
    int zi  = bid & 31;             // z slice (8 units)
    int b0  = bq * 32;
    int grp = bid >> 5;             // dir*4 + bq : 0..7
    int tid = threadIdx.x;
    int kh  = tid >> 7;             // k half
    int wtid = tid & 127;
    int zg  = wtid & 7;             // unit within slice 0..7
    int bg  = wtid >> 3;            // batch pair 0..15
    int bcell = b0 + 2 * bg + kh;   // epilogue cell: batch
    int ucell = zi * 8 + zg;        //                unit

    // load R slice [256 k][32 zc] once (resident all 256 steps)
    {
        const float* Rp = g_Rp[layer][dir] + zi * 32;
        for (int i = tid; i < 2048; i += 256) {
            int k = i >> 3, c = (i & 7) << 2;
            *(float4*)&Rs[k * 32 + c] = *(const float4*)(Rp + (size_t)k * ZZ + c);
        }
    }
    float cc = 0.0f;
    const float* xzb  = g_xz[dir];
    float*       outb = (layer == 0) ? g_h0[dir] : g_h1[dir];

    // prefetch xz for step 0 (this thread's cell)
    float4 xv;
    {
        int t0 = dir ? (TT - 1) : 0;
        xv = *(const float4*)(xzb + (size_t)(t0 * BB + bcell) * ZZ + zi * 32 + zg * 4);
    }
    __syncthreads();

    for (int s = 0; s < TT; s++) {
        int t  = dir ? (TT - 1 - s) : s;
        int rd = s & 1, wr = rd ^ 1;

        // fill h tile [256 k][64] duplicated pairs from g_hT[rd] (L2 loads)
        if (s == 0) {
            float4 z4 = make_float4(0.f, 0.f, 0.f, 0.f);
            for (int i = tid; i < 4096; i += 256) ((float4*)hs)[i] = z4;
        } else {
            const float* src = g_hT[rd][dir] + b0;
#pragma unroll
            for (int r = 0; r < 8; r++) {
                int i = tid + r * 256;            // 0..2047
                int k = i >> 3, q = i & 7;
                float4 v = __ldcg((const float4*)(src + k * BB + q * 4));
                *(float4*)&hs[k * 64 + q * 8]     = make_float4(v.x, v.x, v.y, v.y);
                *(float4*)&hs[k * 64 + q * 8 + 4] = make_float4(v.z, v.z, v.w, v.w);
            }
        }
        __syncthreads();

        // GEMM half: acc (2 b x 4 zc) over 128 k — 2 LDS.128 + 4 FFMA2 per k
        unsigned long long acc[4] = {0ULL, 0ULL, 0ULL, 0ULL};
        {
            const float* hb = hs + kh * 128 * 64 + bg * 4;
            const float* rb = Rs + kh * 128 * 32 + zg * 4;
#pragma unroll 8
            for (int k = 0; k < 128; k++) {
                ulonglong2 hv = *(const ulonglong2*)(hb + k * 64);
                ulonglong2 rv = *(const ulonglong2*)(rb + k * 32);
                fma2(acc[0], hv.x, rv.x);
                fma2(acc[1], hv.x, rv.y);
                fma2(acc[2], hv.y, rv.x);
                fma2(acc[3], hv.y, rv.y);
            }
        }
        // publish partials
        red[tid * 4 + 0] = acc[0];
        red[tid * 4 + 1] = acc[1];
        red[tid * 4 + 2] = acc[2];
        red[tid * 4 + 3] = acc[3];
        __syncthreads();
        // finalize exactly 1 cell (b = bcell, u = ucell)
        {
            const unsigned long long* pr = &red[(tid ^ 128) * 4 + 2 * kh];
            unsigned long long z01 = acc[2 * kh + 0];
            unsigned long long z23 = acc[2 * kh + 1];
            add2(z01, pr[0]);
            add2(z23, pr[1]);
            float z0, z1, z2, z3;
            unpack2(z01, z0, z1);
            unpack2(z23, z2, z3);
            z0 += xv.x; z1 += xv.y; z2 += xv.z; z3 += xv.w;
            float ig = sigm_(z0);
            float fg = sigm_(z1);
            float gg = tanh_(z2);
            float og = sigm_(z3);
            float cn = fmaf(fg, cc, ig * gg);
            cc = cn;
            float hn = og * tanh_(cn);
            g_hT[wr][dir][ucell * BB + bcell] = hn;   // before sync+arrive (validated order)
            stage[zg * 33 + 2 * bg + kh] = hn;
        }
        __syncthreads();

        // ---- group barrier (acq/rel): arrive early, hide work, wait late ----
        if (tid == 0) {
            int old = atom_add_acqrel(&g_count[grp]);
            if (old == 31) {
                g_count[grp] = 0;
                st_release(&g_gen[grp], s + 1);
            }
        }
        // hidden work: sequence output [t][b][u]
        {
            int b = tid >> 3, u = tid & 7;
            outb[(size_t)(t * BB + b0 + b) * UU + zi * 8 + u] = stage[u * 33 + b];
        }
        // hidden work: prefetch xz for next step (independent of h)
        if (s + 1 < TT) {
            int tn2 = dir ? (TT - 2 - s) : (s + 1);
            xv = *(const float4*)(xzb + (size_t)(tn2 * BB + bcell) * ZZ + zi * 32 + zg * 4);
        }
        if (tid == 0) {
            while (ld_acquire(&g_gen[grp]) != s + 1) { }
        }
        __syncthreads();
    }
}

// ---------------- merge: out[b][t][u] = 0.5*(h1f + h0f + h1b + h0b) ---------------
__global__ void merge_kernel(float* __restrict__ out) {
    int i = blockIdx.x * blockDim.x + threadIdx.x;
    if (i >= TT * BB * UU / 4) return;
    int u4 = i & 63;
    int b  = (i >> 6) & 127;
    int t  = i >> 13;
    const float4 a = ((const float4*)g_h1[0])[i];
    const float4 c = ((const float4*)g_h0[0])[i];
    const float4 d = ((const float4*)g_h1[1])[i];
    const float4 e = ((const float4*)g_h0[1])[i];
    float4 r;
    r.x = 0.5f * (a.x + c.x + d.x + e.x);
    r.y = 0.5f * (a.y + c.y + d.y + e.y);
    r.z = 0.5f * (a.z + c.z + d.z + e.z);
    r.w = 0.5f * (a.w + c.w + d.w + e.w);
    ((float4*)out)[((b * TT + t) << 6) + u4] = r;
}

// ---------------- launch ----------------------------------------------------------
extern "C" void kernel_launch(void* const* d_in, const int* in_sizes, int n_in,
                              void* d_out, int out_size) {
    const float* x   = (const float*)d_in[0];
    const float* kfw = (const float*)d_in[1];
    const float* rfw = (const float*)d_in[2];
    const float* bfw = (const float*)d_in[3];
    const float* kbw = (const float*)d_in[4];
    const float* rbw = (const float*)d_in[5];
    const float* bbw = (const float*)d_in[6];
    float* out = (float*)d_out;

    // Rs 32K + hs 64K + red 8K + stage ~1.1K = 107584 bytes -> 2 CTAs/SM (228KB smem)
    const int scan_smem = (256 * 32 + 256 * 64) * 4 + 256 * 4 * 8 + 272 * 4;
    cudaFuncSetAttribute(scan_kernel, cudaFuncAttributeMaxDynamicSharedMemorySize, scan_smem);

    prep_kernel<<<4096, 256>>>(kfw, rfw, bfw, kbw, rbw, bbw);
    for (int layer = 0; layer < 2; layer++) {
        proj_kernel<<<dim3(8, 256, 2), 256>>>(x, layer);
        zero_bar_kernel<<<1, 32>>>();
        scan_kernel<<<NCTA, 256, scan_smem>>>(layer);
    }
    merge_kernel<<<8192, 256>>>(out);
}

// round 12
// speedup vs baseline: 1.1546x; 1.1546x over previous
#include <cuda_runtime.h>

#define BB 128
#define TT 256
#define DD 256
#define UU 256
#define ZZ 1024   // 4*U
#define NPROJ 32
#define NFUSED 288

// ---------------- scratch (device globals; no allocation allowed) ----------------
__device__ float g_xz[2][TT * BB * ZZ];       // layer-0 gate inputs [dir][t][b][u*4+g]
__device__ float g_xz1[2][TT * BB * ZZ];      // layer-1 gate inputs (fused proj output)
__device__ float g_h0[2][TT * BB * UU];       // layer-0 outputs [dir][t][b][u]
__device__ float g_h1[2][TT * BB * UU];       // layer-1 raw lstm outputs
__device__ float g_hTL[2][2][2][UU * BB];     // [layer][buf][dir][u][b] h^T double-buffered
__device__ float g_Wp[2][2][DD * ZZ];         // [layer][dir][k][u*4+g]
__device__ float g_Rp[2][2][UU * ZZ];         // [layer][dir][k][u*4+g]
__device__ float g_bp[2][2][ZZ];
__device__ int g_cnt0[8], g_gen0[8];          // scan0 group barriers (dir x bq)
__device__ int g_cnt1[8], g_gen1[8];          // scan1 group barriers
__device__ int g_projdone[2][TT];             // proj1 tiles done per (dir,t), target 8

// ---------------- packed f32x2 (FFMA2) helpers ------------------------------------
__device__ __forceinline__ void fma2(unsigned long long& d, unsigned long long a,
                                     unsigned long long b) {
    asm("fma.rn.f32x2 %0, %1, %2, %0;" : "+l"(d) : "l"(a), "l"(b));
}
__device__ __forceinline__ void add2(unsigned long long& d, unsigned long long a) {
    asm("add.rn.f32x2 %0, %0, %1;" : "+l"(d) : "l"(a));
}
__device__ __forceinline__ unsigned long long pack2(float x) {
    unsigned long long d; unsigned int u = __float_as_uint(x);
    asm("mov.b64 %0, {%1, %1};" : "=l"(d) : "r"(u));
    return d;
}
__device__ __forceinline__ void unpack2(unsigned long long v, float& lo, float& hi) {
    unsigned int a, b;
    asm("mov.b64 {%0, %1}, %2;" : "=r"(a), "=r"(b) : "l"(v));
    lo = __uint_as_float(a); hi = __uint_as_float(b);
}

// ---------------- acquire/release primitives (CG grid.sync pattern) ----------------
__device__ __forceinline__ int atom_add_acqrel(int* p) {
    int old;
    asm volatile("atom.acq_rel.gpu.global.add.s32 %0, [%1], 1;"
                 : "=r"(old) : "l"(p) : "memory");
    return old;
}
__device__ __forceinline__ void st_release(int* p, int v) {
    asm volatile("st.release.gpu.global.s32 [%0], %1;" :: "l"(p), "r"(v) : "memory");
}
__device__ __forceinline__ int ld_acquire(int* p) {
    int v;
    asm volatile("ld.acquire.gpu.global.s32 %0, [%1];" : "=r"(v) : "l"(p) : "memory");
    return v;
}

// ---------------- cp.async helpers -------------------------------------------------
__device__ __forceinline__ void cpa16(void* smem, const void* g) {
    unsigned s = (unsigned)__cvta_generic_to_shared(smem);
    asm volatile("cp.async.cg.shared.global [%0], [%1], 16;" :: "r"(s), "l"(g));
}
__device__ __forceinline__ void cpa_commit() { asm volatile("cp.async.commit_group;"); }
__device__ __forceinline__ void cpa_wait0()  { asm volatile("cp.async.wait_group 0;"); }

// ---------------- MUFU-free fast math ---------------------------------------------
__device__ __forceinline__ float fast_exp(float x) {
    x = fminf(fmaxf(x, -80.0f), 80.0f);
    float y = x * 1.442695041f;
    float t = y + 12582912.0f;
    float n = t - 12582912.0f;
    float f = y - n;
    int   ni = __float_as_int(t) - 0x4B400000;
    float p = 1.54035304e-4f;
    p = fmaf(p, f, 1.33335581e-3f);
    p = fmaf(p, f, 9.61812910e-3f);
    p = fmaf(p, f, 5.55041087e-2f);
    p = fmaf(p, f, 2.40226507e-1f);
    p = fmaf(p, f, 6.93147182e-1f);
    p = fmaf(p, f, 1.0f);
    return p * __int_as_float((ni + 127) << 23);
}
__device__ __forceinline__ float fast_rcp(float a) {
    float r = __int_as_float(0x7EF311C3 - __float_as_int(a));
    r = r * fmaf(-a, r, 2.0f);
    r = r * fmaf(-a, r, 2.0f);
    r = r * fmaf(-a, r, 2.0f);
    return r;
}
__device__ __forceinline__ float sigm_(float x) { return fast_rcp(1.0f + fast_exp(-x)); }
__device__ __forceinline__ float tanh_(float x) { return fmaf(-2.0f, fast_rcp(1.0f + fast_exp(2.0f * x)), 1.0f); }

// ---------------- weight permutation: col (g*256+u) -> (u*4+g) --------------------
__global__ void prep_kernel(const float* __restrict__ kfw, const float* __restrict__ rfw,
                            const float* __restrict__ bfw, const float* __restrict__ kbw,
                            const float* __restrict__ rbw, const float* __restrict__ bbw) {
    int idx = blockIdx.x * blockDim.x + threadIdx.x;
    if (idx >= 2 * 2 * DD * ZZ) return;
    int e  = idx & (DD * ZZ - 1);
    int ld = idx >> 18;
    int l = ld >> 1, d = ld & 1;
    int k  = e >> 10;
    int uu = e & 1023;
    int u = uu >> 2, g = uu & 3;
    int src_col = g * UU + u;
    const float* Ksrc = d ? kbw : kfw;
    const float* Rsrc = d ? rbw : rfw;
    g_Wp[l][d][e] = Ksrc[l * DD * ZZ + k * ZZ + src_col];
    g_Rp[l][d][e] = Rsrc[l * UU * ZZ + k * ZZ + src_col];
    if (k == 0) {
        const float* bsrc = d ? bbw : bfw;
        g_bp[l][d][uu] = bsrc[l * ZZ + src_col];
    }
}

__global__ void zero_bar_kernel() {
    int i = threadIdx.x;
    if (i < 8) { g_cnt0[i] = 0; g_gen0[i] = 0; g_cnt1[i] = 0; g_gen1[i] = 0; }
    if (i < 512) ((int*)g_projdone)[i] = 0;
}

// ---------------- standalone layer-0 input projection ------------------------------
__global__ __launch_bounds__(256, 2) void proj_kernel(const float* __restrict__ x, int layer) {
    int dir = blockIdx.z;
    const float* A  = x;
    const float* Wp = g_Wp[layer][dir];
    const float* bp = g_bp[layer][dir];
    float* C = g_xz[dir];
    const int m0 = blockIdx.y * 128;
    const int n0 = blockIdx.x * 128;
    __shared__ float As[2][16][128];
    __shared__ float Bs[2][16][128];
    int tid = threadIdx.x;
    int tm = (tid >> 4) << 3;
    int tn = (tid & 15) << 3;
    unsigned long long acc2[8][4];
#pragma unroll
    for (int i = 0; i < 8; i++)
#pragma unroll
        for (int j = 0; j < 4; j++) acc2[i][j] = 0ULL;

    int arow = tid >> 1, akq = (tid & 1) << 3;
    int brow = tid >> 4, bc = (tid & 15) << 3;
    const float* Ap = A + (size_t)(m0 + arow) * DD + akq;
    const float* Bp = Wp + (size_t)brow * ZZ + n0 + bc;

    {
        float4 a0 = *(const float4*)Ap;
        float4 a1 = *(const float4*)(Ap + 4);
        As[0][akq + 0][arow] = a0.x; As[0][akq + 1][arow] = a0.y;
        As[0][akq + 2][arow] = a0.z; As[0][akq + 3][arow] = a0.w;
        As[0][akq + 4][arow] = a1.x; As[0][akq + 5][arow] = a1.y;
        As[0][akq + 6][arow] = a1.z; As[0][akq + 7][arow] = a1.w;
    }
    cpa16(&Bs[0][brow][bc], Bp);
    cpa16(&Bs[0][brow][bc + 4], Bp + 4);
    cpa_commit();
    float4 av0 = *(const float4*)(Ap + 16);
    float4 av1 = *(const float4*)(Ap + 20);

    for (int it = 0; it < 16; it++) {
        int cur = it & 1, nxt = cur ^ 1;
        cpa_wait0();
        __syncthreads();
        if (it < 15) {
            As[nxt][akq + 0][arow] = av0.x; As[nxt][akq + 1][arow] = av0.y;
            As[nxt][akq + 2][arow] = av0.z; As[nxt][akq + 3][arow] = av0.w;
            As[nxt][akq + 4][arow] = av1.x; As[nxt][akq + 5][arow] = av1.y;
            As[nxt][akq + 6][arow] = av1.z; As[nxt][akq + 7][arow] = av1.w;
            cpa16(&Bs[nxt][brow][bc], Bp + (size_t)(it + 1) * 16 * ZZ);
            cpa16(&Bs[nxt][brow][bc + 4], Bp + (size_t)(it + 1) * 16 * ZZ + 4);
            cpa_commit();
            if (it < 14) {
                av0 = *(const float4*)(Ap + (it + 2) * 16);
                av1 = *(const float4*)(Ap + (it + 2) * 16 + 4);
            }
        }
#pragma unroll
        for (int kk = 0; kk < 16; kk++) {
            float a[8];
            *(float4*)&a[0] = *(float4*)&As[cur][kk][tm];
            *(float4*)&a[4] = *(float4*)&As[cur][kk][tm + 4];
            ulonglong2 b01 = *(const ulonglong2*)&Bs[cur][kk][tn];
            ulonglong2 b23 = *(const ulonglong2*)&Bs[cur][kk][tn + 4];
#pragma unroll
            for (int i = 0; i < 8; i++) {
                unsigned long long ai = pack2(a[i]);
                fma2(acc2[i][0], ai, b01.x);
                fma2(acc2[i][1], ai, b01.y);
                fma2(acc2[i][2], ai, b23.x);
                fma2(acc2[i][3], ai, b23.y);
            }
        }
    }
    float bv[8];
#pragma unroll
    for (int j = 0; j < 8; j++) bv[j] = bp[n0 + tn + j];
#pragma unroll
    for (int i = 0; i < 8; i++) {
        int m = m0 + tm + i;
        int crow = (m & 255) * BB + (m >> 8);   // layer0: A row b*256+t -> C row t*128+b
        float* cp = C + (size_t)crow * ZZ + n0 + tn;
        float c0, c1, c2, c3, c4, c5, c6, c7;
        unpack2(acc2[i][0], c0, c1);
        unpack2(acc2[i][1], c2, c3);
        unpack2(acc2[i][2], c4, c5);
        unpack2(acc2[i][3], c6, c7);
        float4 v0, v1;
        v0.x = c0 + bv[0]; v0.y = c1 + bv[1]; v0.z = c2 + bv[2]; v0.w = c3 + bv[3];
        v1.x = c4 + bv[4]; v1.y = c5 + bv[5]; v1.z = c6 + bv[6]; v1.w = c7 + bv[7];
        *(float4*)cp = v0;
        *(float4*)(cp + 4) = v1;
    }
}

// ---------------- fused pipeline bodies --------------------------------------------

// scan body: R10 structure. sub in [0,128): (dir, batch-quarter 32b, 16-unit z-slice).
__device__ __forceinline__ void scan_body(int layer, int sub, float* sm) {
    float* Rs = sm;                                   // 64 KB
    float* hs = sm + UU * 64;                         // 32 KB
    unsigned long long* red = (unsigned long long*)(hs + UU * 32);  // 256*4 u64 = 8 KB
    float* stage = (float*)(red + 256 * 4);           // 2 KB

    int dir  = sub >> 6;
    int rest = sub & 63;
    int b0  = (rest >> 4) * 32;
    int zi  = rest & 15;
    int zc0 = zi * 64;
    int u0  = zi * 16;
    int grp = sub >> 4;
    int tid = threadIdx.x;
    int kh   = tid >> 7;
    int wtid = tid & 127;
    int zg  = wtid & 15;
    int bgr = wtid >> 4;
    int bb  = b0 + bgr * 4 + kh * 2;

    int* cnt = layer ? g_cnt1 : g_cnt0;
    int* gen = layer ? g_gen1 : g_gen0;
    const float* xzb  = (layer ? g_xz1 : g_xz)[dir];
    float*       outb = (layer ? g_h1 : g_h0)[dir];

    // load R slice once
    {
        const float* Rp = g_Rp[layer][dir];
        float4* Rs4 = (float4*)Rs;
        for (int idx = tid; idx < 4096; idx += 256) {
            int k = idx >> 4, c = idx & 15;
            Rs4[idx] = *(const float4*)(Rp + k * ZZ + zc0 + c * 4);
        }
    }
    float cc[2] = {0.0f, 0.0f};

    // step-0 xz (layer1: gate on proj completion first)
    int t0 = dir ? (TT - 1) : 0;
    if (layer) {
        if (tid == 0) { while (ld_acquire(&g_projdone[dir][t0]) < 8) { } }
        __syncthreads();
    }
    float4 xv[2];
    {
        const float* xp = xzb + (size_t)(t0 * BB + bb) * ZZ + zc0 + zg * 4;
        xv[0] = *(const float4*)(xp);
        xv[1] = *(const float4*)(xp + ZZ);
    }
    __syncthreads();

    for (int s = 0; s < TT; s++) {
        int t  = dir ? (TT - 1 - s) : s;
        int rd = s & 1, wr = rd ^ 1;

        // fill h tile [256 k][32 b]
        float4* hs4 = (float4*)hs;
        if (s == 0) {
            for (int idx = tid; idx < 2048; idx += 256)
                hs4[idx] = make_float4(0.f, 0.f, 0.f, 0.f);
        } else {
            const float4* src = (const float4*)(g_hTL[layer][rd][dir]);
            for (int idx = tid; idx < 2048; idx += 256) {
                int k = idx >> 3, q = idx & 7;
                cpa16(&hs4[idx], src + k * 32 + (b0 >> 2) + q);
            }
            cpa_commit();
            cpa_wait0();
        }
        __syncthreads();

        // GEMM half: acc(4b x 4zc) over 128 k
        unsigned long long acc[8];
#pragma unroll
        for (int j = 0; j < 8; j++) acc[j] = 0ULL;
        {
            const float* hrow = hs + kh * 128 * 32 + bgr * 4;
            const float* rrow = Rs + kh * 128 * 64 + zg * 4;
#pragma unroll 4
            for (int k = 0; k < 128; k++) {
                float4 hv = *(const float4*)(hrow + k * 32);
                ulonglong2 rv = *(const ulonglong2*)(rrow + k * 64);
                unsigned long long h0 = pack2(hv.x), h1 = pack2(hv.y);
                unsigned long long h2 = pack2(hv.z), h3 = pack2(hv.w);
                fma2(acc[0], h0, rv.x); fma2(acc[1], h0, rv.y);
                fma2(acc[2], h1, rv.x); fma2(acc[3], h1, rv.y);
                fma2(acc[4], h2, rv.x); fma2(acc[5], h2, rv.y);
                fma2(acc[6], h3, rv.x); fma2(acc[7], h3, rv.y);
            }
        }
        // publish only the half this thread won't finalize (partner needs it)
        {
            int oh = (kh ^ 1) * 4;
#pragma unroll
            for (int j = 0; j < 4; j++) red[tid * 4 + j] = acc[oh + j];
        }
        __syncthreads();
        // finalize 2 cells (b = bb, bb+1 ; u = u0+zg)
        {
            const unsigned long long* pr = &red[(tid ^ 128) * 4];
            float hn[2];
#pragma unroll
            for (int ii = 0; ii < 2; ii++) {
                int i = kh * 2 + ii;
                unsigned long long z01 = acc[i * 2 + 0];
                unsigned long long z23 = acc[i * 2 + 1];
                add2(z01, pr[ii * 2 + 0]);
                add2(z23, pr[ii * 2 + 1]);
                float z0, z1, z2, z3;
                unpack2(z01, z0, z1);
                unpack2(z23, z2, z3);
                z0 += xv[ii].x; z1 += xv[ii].y; z2 += xv[ii].z; z3 += xv[ii].w;
                float ig = sigm_(z0);
                float fg = sigm_(z1);
                float gg = tanh_(z2);
                float og = sigm_(z3);
                float cn = fmaf(fg, cc[ii], ig * gg);
                cc[ii] = cn;
                hn[ii] = og * tanh_(cn);
            }
            int u = u0 + zg;
            *(float2*)(g_hTL[layer][wr][dir] + u * BB + bb) = make_float2(hn[0], hn[1]);
            stage[(bgr * 4 + kh * 2 + 0) * 16 + zg] = hn[0];
            stage[(bgr * 4 + kh * 2 + 1) * 16 + zg] = hn[1];
        }
        __syncthreads();
        // sequence output BEFORE arrive: release-sequence publishes h0[t] to proj CTAs
        if (tid < 128) {
            int row = tid >> 2, q = tid & 3;
            *(float4*)(outb + (size_t)(t * BB + b0 + row) * UU + u0 + q * 4) =
                ((float4*)stage)[tid];
        }
        __syncthreads();

        // group barrier (acq/rel): arrive, hide xz prefetch, wait
        if (tid == 0) {
            int old = atom_add_acqrel(&cnt[grp]);
            if (old == 15) {
                cnt[grp] = 0;
                st_release(&gen[grp], s + 1);
            }
        }
        if (s + 1 < TT) {
            int tn2 = dir ? (TT - 2 - s) : (s + 1);
            if (layer) {
                if (tid == 0) { while (ld_acquire(&g_projdone[dir][tn2]) < 8) { } }
                __syncthreads();
            }
            const float* xp = xzb + (size_t)(tn2 * BB + bb) * ZZ + zc0 + zg * 4;
            xv[0] = *(const float4*)(xp);
            xv[1] = *(const float4*)(xp + ZZ);
        }
        if (tid == 0) {
            while (ld_acquire(&gen[grp]) != s + 1) { }
        }
        __syncthreads();
    }
}

// proj1 body: persistent, grid-strides 4096 tiles (dir, t, n-block of 128).
// A = h0[dir] rows [t*128, t*128+128)  (the m-block IS the time step).
__device__ __forceinline__ void proj1_body(int pid, float* sm) {
    float* As = sm;            // 2 bufs x 16 x 128
    float* Bs = sm + 4096;     // 2 bufs x 16 x 128
    int tid = threadIdx.x;
    int tm = (tid >> 4) << 3;
    int tn = (tid & 15) << 3;
    int arow = tid >> 1, akq = (tid & 1) << 3;
    int brow = tid >> 4, bc = (tid & 15) << 3;

    for (int j = pid; j < 4096; j += NPROJ) {
        int dir = j & 1;
        int r   = j >> 1;
        int q   = r >> 3;
        int nb  = r & 7;
        int t   = dir ? (TT - 1 - q) : q;
        // gate: h0[dir][t] complete after scan0 step q across all 4 batch groups
        if (tid == 0) {
            int base = dir * 4;
            while (ld_acquire(&g_gen0[base + 0]) < q + 1) { }
            while (ld_acquire(&g_gen0[base + 1]) < q + 1) { }
            while (ld_acquire(&g_gen0[base + 2]) < q + 1) { }
            while (ld_acquire(&g_gen0[base + 3]) < q + 1) { }
        }
        __syncthreads();

        const float* A   = g_h0[dir] + (size_t)t * 128 * DD;
        const float* Wp  = g_Wp[1][dir];
        const float* bpv = g_bp[1][dir];
        float* C = g_xz1[dir] + (size_t)t * 128 * ZZ;
        int n0 = nb * 128;

        unsigned long long acc2[8][4];
#pragma unroll
        for (int i = 0; i < 8; i++)
#pragma unroll
            for (int jj = 0; jj < 4; jj++) acc2[i][jj] = 0ULL;

        const float* Ap = A + (size_t)arow * DD + akq;
        const float* Bp = Wp + (size_t)brow * ZZ + n0 + bc;
        {
            float4 a0 = __ldcg((const float4*)Ap);
            float4 a1 = __ldcg((const float4*)(Ap + 4));
            As[(akq + 0) * 128 + arow] = a0.x; As[(akq + 1) * 128 + arow] = a0.y;
            As[(akq + 2) * 128 + arow] = a0.z; As[(akq + 3) * 128 + arow] = a0.w;
            As[(akq + 4) * 128 + arow] = a1.x; As[(akq + 5) * 128 + arow] = a1.y;
            As[(akq + 6) * 128 + arow] = a1.z; As[(akq + 7) * 128 + arow] = a1.w;
        }
        cpa16(&Bs[brow * 128 + bc], Bp);
        cpa16(&Bs[brow * 128 + bc + 4], Bp + 4);
        cpa_commit();
        float4 av0 = __ldcg((const float4*)(Ap + 16));
        float4 av1 = __ldcg((const float4*)(Ap + 20));

        for (int it = 0; it < 16; it++) {
            int cur = it & 1, nxt = cur ^ 1;
            float* Ac = As + cur * 2048;
            float* Bc = Bs + cur * 2048;
            cpa_wait0();
            __syncthreads();
            if (it < 15) {
                float* An = As + nxt * 2048;
                An[(akq + 0) * 128 + arow] = av0.x; An[(akq + 1) * 128 + arow] = av0.y;
                An[(akq + 2) * 128 + arow] = av0.z; An[(akq + 3) * 128 + arow] = av0.w;
                An[(akq + 4) * 128 + arow] = av1.x; An[(akq + 5) * 128 + arow] = av1.y;
                An[(akq + 6) * 128 + arow] = av1.z; An[(akq + 7) * 128 + arow] = av1.w;
                cpa16(&Bs[nxt * 2048 + brow * 128 + bc], Bp + (size_t)(it + 1) * 16 * ZZ);
                cpa16(&Bs[nxt * 2048 + brow * 128 + bc + 4], Bp + (size_t)(it + 1) * 16 * ZZ + 4);
                cpa_commit();
                if (it < 14) {
                    av0 = __ldcg((const float4*)(Ap + (it + 2) * 16));
                    av1 = __ldcg((const float4*)(Ap + (it + 2) * 16 + 4));
                }
            }
#pragma unroll
            for (int kk = 0; kk < 16; kk++) {
                float a[8];
                *(float4*)&a[0] = *(float4*)&Ac[kk * 128 + tm];
                *(float4*)&a[4] = *(float4*)&Ac[kk * 128 + tm + 4];
                ulonglong2 b01 = *(const ulonglong2*)&Bc[kk * 128 + tn];
                ulonglong2 b23 = *(const ulonglong2*)&Bc[kk * 128 + tn + 4];
#pragma unroll
                for (int i = 0; i < 8; i++) {
                    unsigned long long ai = pack2(a[i]);
                    fma2(acc2[i][0], ai, b01.x);
                    fma2(acc2[i][1], ai, b01.y);
                    fma2(acc2[i][2], ai, b23.x);
                    fma2(acc2[i][3], ai, b23.y);
                }
            }
        }
        float bv[8];
#pragma unroll
        for (int jj = 0; jj < 8; jj++) bv[jj] = bpv[n0 + tn + jj];
#pragma unroll
        for (int i = 0; i < 8; i++) {
            float* cp = C + (size_t)(tm + i) * ZZ + n0 + tn;
            float c0, c1, c2, c3, c4, c5, c6, c7;
            unpack2(acc2[i][0], c0, c1);
            unpack2(acc2[i][1], c2, c3);
            unpack2(acc2[i][2], c4, c5);
            unpack2(acc2[i][3], c6, c7);
            float4 v0, v1;
            v0.x = c0 + bv[0]; v0.y = c1 + bv[1]; v0.z = c2 + bv[2]; v0.w = c3 + bv[3];
            v1.x = c4 + bv[4]; v1.y = c5 + bv[5]; v1.z = c6 + bv[6]; v1.w = c7 + bv[7];
            *(float4*)cp = v0;
            *(float4*)(cp + 4) = v1;
        }
        __syncthreads();   // all C stores in program order before the release add
        if (tid == 0) atom_add_acqrel(&g_projdone[dir][t]);
    }
}

// fused pipeline: 288 CTAs, 2/SM (capacity 296) -> all resident; deps acyclic.
__global__ __launch_bounds__(256, 2) void fused_kernel() {
    extern __shared__ float sm[];
    int bid = blockIdx.x;
    if (bid < 128)      scan_body(0, bid, sm);
    else if (bid < 256) scan_body(1, bid - 128, sm);
    else                proj1_body(bid - 256, sm);
}

// ---------------- merge: out[b][t][u] = 0.5*(h1f + h0f + h1b + h0b) ---------------
__global__ void merge_kernel(float* __restrict__ out) {
    int i = blockIdx.x * blockDim.x + threadIdx.x;
    if (i >= TT * BB * UU / 4) return;
    int u4 = i & 63;
    int b  = (i >> 6) & 127;
    int t  = i >> 13;
    const float4 a = ((const float4*)g_h1[0])[i];
    const float4 c = ((const float4*)g_h0[0])[i];
    const float4 d = ((const float4*)g_h1[1])[i];
    const float4 e = ((const float4*)g_h0[1])[i];
    float4 r;
    r.x = 0.5f * (a.x + c.x + d.x + e.x);
    r.y = 0.5f * (a.y + c.y + d.y + e.y);
    r.z = 0.5f * (a.z + c.z + d.z + e.z);
    r.w = 0.5f * (a.w + c.w + d.w + e.w);
    ((float4*)out)[((b * TT + t) << 6) + u4] = r;
}

// ---------------- launch ----------------------------------------------------------
extern "C" void kernel_launch(void* const* d_in, const int* in_sizes, int n_in,
                              void* d_out, int out_size) {
    const float* x   = (const float*)d_in[0];
    const float* kfw = (const float*)d_in[1];
    const float* rfw = (const float*)d_in[2];
    const float* bfw = (const float*)d_in[3];
    const float* kbw = (const float*)d_in[4];
    const float* rbw = (const float*)d_in[5];
    const float* bbw = (const float*)d_in[6];
    float* out = (float*)d_out;

    // Rs 64K + hs 32K + red 8K + stage 2K = 108544 bytes -> 2 CTAs/SM
    const int fused_smem = (UU * 64 + UU * 32) * 4 + 256 * 4 * 8 + 2048;
    cudaFuncSetAttribute(fused_kernel, cudaFuncAttributeMaxDynamicSharedMemorySize, fused_smem);

    prep_kernel<<<4096, 256>>>(kfw, rfw, bfw, kbw, rbw, bbw);
    zero_bar_kernel<<<1, 512>>>();
    proj_kernel<<<dim3(8, 256, 2), 256>>>(x, 0);
    fused_kernel<<<NFUSED, 256, fused_smem>>>();
    merge_kernel<<<8192, 256>>>(out);
}